// round 7
// baseline (speedup 1.0000x reference)
#include <cuda_runtime.h>
#include <cuda_bf16.h>
#include <cstdint>
#include <math.h>

// Problem constants
#define B_  2
#define C1_ 256
#define C2_ 256
#define K2_ 9
#define H_  64
#define W_  64
#define HW_ 4096

// ---------------------------------------------------------------------------
// Scratch (allocation-free: __device__ globals)
// ---------------------------------------------------------------------------
// Main weights: [step(36)=tap*4+chunk][hl(2)][o(256)][72 bf16]
__device__ __align__(128) __nv_bfloat16 g_wA[36 * 2 * 256 * 72];
// Conv weights: [step(36)=kk*4+chunk][hl(2)][ocpad(32)][72 bf16]
__device__ __align__(128) __nv_bfloat16 g_wC[36 * 2 * 32 * 72];

// ---------------------------------------------------------------------------
// PTX helpers (plain sm_103-legal)
// ---------------------------------------------------------------------------
__device__ __forceinline__ uint32_t smem_u32(const void* p) {
    uint32_t a;
    asm("{ .reg .u64 t; cvta.to.shared.u64 t, %1; cvt.u32.u64 %0, t; }"
        : "=r"(a) : "l"(p));
    return a;
}
__device__ __forceinline__ void cp_async16(uint32_t saddr, const void* gaddr) {
    asm volatile("cp.async.cg.shared.global [%0], [%1], 16;"
                 :: "r"(saddr), "l"(gaddr) : "memory");
}
__device__ __forceinline__ void cp_commit() {
    asm volatile("cp.async.commit_group;" ::: "memory");
}
__device__ __forceinline__ void cp_wait1() {
    asm volatile("cp.async.wait_group 1;" ::: "memory");
}
__device__ __forceinline__ void cp_wait0() {
    asm volatile("cp.async.wait_group 0;" ::: "memory");
}
__device__ __forceinline__ void bar_sync(int id, int cnt) {
    asm volatile("bar.sync %0, %1;" :: "r"(id), "r"(cnt) : "memory");
}
__device__ __forceinline__ void ldmatrix_x4(uint32_t& r0, uint32_t& r1,
                                            uint32_t& r2, uint32_t& r3,
                                            uint32_t addr) {
    asm volatile("ldmatrix.sync.aligned.m8n8.x4.shared.b16 {%0,%1,%2,%3}, [%4];"
                 : "=r"(r0), "=r"(r1), "=r"(r2), "=r"(r3) : "r"(addr));
}
__device__ __forceinline__ void mma_bf16(float& d0, float& d1, float& d2, float& d3,
                                         uint32_t a0, uint32_t a1, uint32_t a2, uint32_t a3,
                                         uint32_t b0, uint32_t b1) {
    asm volatile(
        "mma.sync.aligned.m16n8k16.row.col.f32.bf16.bf16.f32 "
        "{%0,%1,%2,%3}, {%4,%5,%6,%7}, {%8,%9}, {%0,%1,%2,%3};"
        : "+f"(d0), "+f"(d1), "+f"(d2), "+f"(d3)
        : "r"(a0), "r"(a1), "r"(a2), "r"(a3), "r"(b0), "r"(b1));
}

// ---------------------------------------------------------------------------
// Kernel 0: pack w_dcn + w_off into bf16 hi/lo blobs
// ---------------------------------------------------------------------------
__global__ void pack_weights(const float* __restrict__ w_dcn,
                             const float* __restrict__ w_off) {
    int idx = blockIdx.x * 256 + threadIdx.x;
    if (idx < 9 * 256 * 256) {
        int t = idx >> 16;
        int r = idx & 65535;
        int o = r >> 8;
        int c = r & 255;
        float w = w_dcn[o * (C1_ * K2_) + c * K2_ + t];
        __nv_bfloat16 hi = __float2bfloat16(w);
        __nv_bfloat16 lo = __float2bfloat16(w - __bfloat162float(hi));
        int chunk = c >> 6, cl = c & 63;
        size_t base = ((size_t)(t * 4 + chunk) * 2) * (256 * 72) + (size_t)o * 72 + cl;
        g_wA[base]            = hi;
        g_wA[base + 256 * 72] = lo;
    }
    if (idx < 27 * 2304) {
        int oc = idx / 2304;
        int r  = idx % 2304;
        int c  = r / 9;
        int kk = r % 9;
        float w = w_off[idx];
        __nv_bfloat16 hi = __float2bfloat16(w);
        __nv_bfloat16 lo = __float2bfloat16(w - __bfloat162float(hi));
        int s = kk * 4 + (c >> 6);
        int cl = c & 63;
        size_t base = (size_t)s * (2 * 32 * 72) + (size_t)oc * 72 + cl;
        g_wC[base]           = hi;
        g_wC[base + 32 * 72] = lo;
    }
}

// ---------------------------------------------------------------------------
// Fused kernel, 512 threads: warps 0-7 consumers, 8-15 producers.
// Phase 1: offset-conv GEMM -> om smem. Phase 2: DCN GEMM + BN + SiLU.
// ---------------------------------------------------------------------------
#define WROW     72
#define WROWB    144
#define BHL2_B   4608u       // per-hl weight slice per warp (32 rows x 144B)
#define WBUF2_B  9216u       // one buffer (hi+lo)
#define WWARP2_B 18432u      // two buffers
#define BBASE    147456u     // 8 * WWARP2_B
#define BBUF_B   18432u
#define BHL_B    9216u
#define META_O   184320u
// META: swt[256]f (1024) | sidx[256]i (1024) | om[32*64]f (8192)
#define SMEM_BYTES (META_O + 2048u + 8192u)

__global__ __launch_bounds__(512, 1) void dcn_fused(const float* __restrict__ x,
                                                    const float* __restrict__ b_off,
                                                    const float* __restrict__ gamma,
                                                    const float* __restrict__ beta,
                                                    const float* __restrict__ rmean,
                                                    const float* __restrict__ rvar,
                                                    float* __restrict__ out) {
    extern __shared__ __align__(128) unsigned char smem_raw[];
    const uint32_t smem_base = smem_u32(smem_raw);

    int b = blockIdx.x >> 6;
    int h = blockIdx.x & 63;
    int tid = threadIdx.x;
    int wid = tid >> 5;
    int lane = tid & 31;

    float* swt  = (float*)(smem_raw + META_O);
    int*   sidx = (int*)(smem_raw + META_O + 1024);
    float* om   = (float*)(smem_raw + META_O + 2048);   // [oc][64]
    const float* xb = x + b * C1_ * HW_;

    if (wid >= 8) {
        // ========================= PRODUCERS (8 warps) =========================
        int ptid = tid - 256;
        int p  = ptid & 63;
        int cg = ptid >> 6;      // 0..3 -> 16 channels each

        auto conv_chunk = [&](int s) {
            int kk = s >> 2, q = s & 3;
            int ky = kk / 3, kx = kk % 3;
            int y = h - 1 + ky;
            int col = p - 1 + kx;
            bool valid = (y >= 0) && (y < H_) && (col >= 0) && (col < W_);
            unsigned char* Bb = smem_raw + BBASE + (uint32_t)(s & 1) * BBUF_B;
            uint32_t rowoff = (uint32_t)p * WROWB;
#pragma unroll
            for (int it = 0; it < 8; ++it) {
                int cl = cg * 16 + it * 2;
                int c0 = q * 64 + cl;
                float va = 0.f, vb = 0.f;
                if (valid) {
                    const float* xa = xb + ((size_t)c0 << 12) + y * W_ + col;
                    va = xa[0];
                    vb = xa[HW_];
                }
                __nv_bfloat162 hp = __floats2bfloat162_rn(va, vb);
                float ra = va - __bfloat162float(hp.x);
                float rb = vb - __bfloat162float(hp.y);
                __nv_bfloat162 lp = __floats2bfloat162_rn(ra, rb);
                uint32_t a = rowoff + (uint32_t)cl * 2;
                *(__nv_bfloat162*)(Bb + a)         = hp;
                *(__nv_bfloat162*)(Bb + BHL_B + a) = lp;
            }
        };

        conv_chunk(0);
        bar_sync(1, 512);
        for (int s = 0; s < 36; ++s) {
            if (s < 35) conv_chunk(s + 1);
            bar_sync(1, 512);
        }
        bar_sync(1, 512);        // consumers write om

        auto make_meta = [&](int t) {
            if (ptid < 64) {
                int w = ptid;
                float py = (float)(h - 1 + t / 3) + om[(2 * t) * 64 + w];
                float px = (float)(w - 1 + t % 3) + om[(2 * t + 1) * 64 + w];
                float m = 1.f / (1.f + __expf(-om[(18 + t) * 64 + w]));
                float y0f = floorf(py), x0f = floorf(px);
                float ly = py - y0f, lx = px - x0f;
                int y0 = (int)y0f, x0 = (int)x0f;
                int y1 = y0 + 1, x1 = x0 + 1;
                float vy0 = (y0 >= 0 && y0 < H_) ? 1.f : 0.f;
                float vy1 = (y1 >= 0 && y1 < H_) ? 1.f : 0.f;
                float vx0 = (x0 >= 0 && x0 < W_) ? 1.f : 0.f;
                float vx1 = (x1 >= 0 && x1 < W_) ? 1.f : 0.f;
                int cy0 = min(max(y0, 0), H_ - 1), cy1 = min(max(y1, 0), H_ - 1);
                int cx0 = min(max(x0, 0), W_ - 1), cx1 = min(max(x1, 0), W_ - 1);
                swt[0 * 64 + w] = (1.f - ly) * (1.f - lx) * m * vy0 * vx0;
                swt[1 * 64 + w] = (1.f - ly) * lx * m * vy0 * vx1;
                swt[2 * 64 + w] = ly * (1.f - lx) * m * vy1 * vx0;
                swt[3 * 64 + w] = ly * lx * m * vy1 * vx1;
                sidx[0 * 64 + w] = cy0 * W_ + cx0;
                sidx[1 * 64 + w] = cy0 * W_ + cx1;
                sidx[2 * 64 + w] = cy1 * W_ + cx0;
                sidx[3 * 64 + w] = cy1 * W_ + cx1;
            }
            bar_sync(2, 256);
        };

        auto make_chunk = [&](int s) {
            int q = s & 3;
            int i0 = sidx[p],       i1 = sidx[64 + p];
            int i2 = sidx[128 + p], i3 = sidx[192 + p];
            float w0 = swt[p],       w1 = swt[64 + p];
            float w2 = swt[128 + p], w3 = swt[192 + p];
            unsigned char* Bb = smem_raw + BBASE + (uint32_t)(s & 1) * BBUF_B;
            uint32_t rowoff = (uint32_t)p * WROWB;
#pragma unroll
            for (int it = 0; it < 8; ++it) {
                int cl = cg * 16 + it * 2;
                int c0 = q * 64 + cl;
                const float* xa = xb + ((size_t)c0 << 12);
                const float* xc = xa + HW_;
                float va = xa[i0] * w0 + xa[i1] * w1 + xa[i2] * w2 + xa[i3] * w3;
                float vb = xc[i0] * w0 + xc[i1] * w1 + xc[i2] * w2 + xc[i3] * w3;
                __nv_bfloat162 hp = __floats2bfloat162_rn(va, vb);
                float ra = va - __bfloat162float(hp.x);
                float rb = vb - __bfloat162float(hp.y);
                __nv_bfloat162 lp = __floats2bfloat162_rn(ra, rb);
                uint32_t a = rowoff + (uint32_t)cl * 2;
                *(__nv_bfloat162*)(Bb + a)         = hp;
                *(__nv_bfloat162*)(Bb + BHL_B + a) = lp;
            }
        };

        make_meta(0);
        make_chunk(0);
        bar_sync(1, 512);
        for (int s = 0; s < 36; ++s) {
            if (s < 35) {
                int ns = s + 1;
                if ((ns & 3) == 0) make_meta(ns >> 2);
                make_chunk(ns);
            }
            bar_sync(1, 512);
        }
    } else {
        // ========================= CONSUMERS (8 warps) =========================
        int a_row = lane & 15;
        int a_cad = (lane >= 16) ? 8 : 0;
        int b_row = (lane & 7) + ((lane >= 16) ? 8 : 0);
        int b_cad = ((lane >> 3) & 1) * 8;
        int g4 = lane >> 2;
        int t4 = lane & 3;

        uint32_t wdst0 = smem_base + (uint32_t)wid * WWARP2_B;

        // ---- phase 1: conv MMA (m=32 oc; warp owns 8 px)
        {
            int rgn  = wid >> 1;        // 16-px region 0..3
            int half = wid & 1;         // which 8-px n-tile within region

            float accC[2][4];
#pragma unroll
            for (int mt = 0; mt < 2; mt++)
#pragma unroll
                for (int j = 0; j < 4; j++) accC[mt][j] = 0.f;

            auto cpWC = [&](int s) {
                const unsigned char* src =
                    (const unsigned char*)g_wC + (size_t)s * 9216u;
                uint32_t dst = wdst0 + (uint32_t)(s & 1) * WBUF2_B;
#pragma unroll
                for (int hl = 0; hl < 2; ++hl) {
#pragma unroll
                    for (int j = 0; j < 9; ++j) {       // 9*32*16B = 4608B
                        uint32_t off = (uint32_t)(lane + j * 32) * 16u;
                        cp_async16(dst + (uint32_t)hl * BHL2_B + off,
                                   src + (size_t)hl * 4608u + off);
                    }
                }
                cp_commit();
            };

            cpWC(0);
            bar_sync(1, 512);

            for (int s = 0; s < 36; ++s) {
                if (s < 35) { cpWC(s + 1); cp_wait1(); }
                else        { cp_wait0(); }

                uint32_t wreg = wdst0 + (uint32_t)(s & 1) * WBUF2_B;
                uint32_t breg = smem_base + BBASE + (uint32_t)(s & 1) * BBUF_B;

#pragma unroll
                for (int ks = 0; ks < 4; ++ks) {
                    uint32_t addrB = breg +
                        (uint32_t)((rgn * 16 + b_row) * WROW + ks * 16 + b_cad) * 2;
                    uint32_t Bh0, Bh1, Bh2, Bh3, Bl0, Bl1, Bl2, Bl3;
                    ldmatrix_x4(Bh0, Bh1, Bh2, Bh3, addrB);
                    ldmatrix_x4(Bl0, Bl1, Bl2, Bl3, addrB + BHL_B);
                    uint32_t bh0 = half ? Bh2 : Bh0, bh1 = half ? Bh3 : Bh1;
                    uint32_t bl0 = half ? Bl2 : Bl0, bl1 = half ? Bl3 : Bl1;
#pragma unroll
                    for (int mt = 0; mt < 2; ++mt) {
                        uint32_t aaddr = wreg +
                            (uint32_t)((mt * 16 + a_row) * WROW + ks * 16 + a_cad) * 2;
                        uint32_t Ah0, Ah1, Ah2, Ah3, Al0, Al1, Al2, Al3;
                        ldmatrix_x4(Ah0, Ah1, Ah2, Ah3, aaddr);
                        ldmatrix_x4(Al0, Al1, Al2, Al3, aaddr + BHL2_B);
                        float* d = accC[mt];
                        mma_bf16(d[0], d[1], d[2], d[3], Ah0, Ah1, Ah2, Ah3, bh0, bh1);
                        mma_bf16(d[0], d[1], d[2], d[3], Ah0, Ah1, Ah2, Ah3, bl0, bl1);
                        mma_bf16(d[0], d[1], d[2], d[3], Al0, Al1, Al2, Al3, bh0, bh1);
                    }
                }
                bar_sync(1, 512);
            }

            // conv epilogue -> om smem (+ bias). Warp writes its 8 px.
            int col0 = rgn * 16 + half * 8;
#pragma unroll
            for (int mt = 0; mt < 2; ++mt) {
                int oc_lo = mt * 16 + g4;
                int oc_hi = oc_lo + 8;
                int col = col0 + t4 * 2;
                if (oc_lo < 27) {
                    float bo = b_off[oc_lo];
                    om[oc_lo * 64 + col]     = accC[mt][0] + bo;
                    om[oc_lo * 64 + col + 1] = accC[mt][1] + bo;
                }
                if (oc_hi < 27) {
                    float bo = b_off[oc_hi];
                    om[oc_hi * 64 + col]     = accC[mt][2] + bo;
                    om[oc_hi * 64 + col + 1] = accC[mt][3] + bo;
                }
            }
            bar_sync(1, 512);    // om ready for producers
        }

        // ---- phase 2: main DCN MMA (warp owns o in [32w, 32w+32))
        int o0 = wid * 32;
        float acc[2][8][4];
#pragma unroll
        for (int mt = 0; mt < 2; mt++)
#pragma unroll
            for (int nt = 0; nt < 8; nt++)
#pragma unroll
                for (int j = 0; j < 4; j++) acc[mt][nt][j] = 0.f;

        const unsigned char* wsrc0 = (const unsigned char*)g_wA +
                                     (size_t)wid * 4608u;

        auto cpW = [&](int s) {
            const unsigned char* src = wsrc0 + (size_t)s * 73728u;
            uint32_t dst = wdst0 + (uint32_t)(s & 1) * WBUF2_B;
#pragma unroll
            for (int hl = 0; hl < 2; ++hl) {
#pragma unroll
                for (int j = 0; j < 9; ++j) {           // 9*32*16B = 4608B
                    uint32_t off = (uint32_t)(lane + j * 32) * 16u;
                    cp_async16(dst + (uint32_t)hl * BHL2_B + off,
                               src + (size_t)hl * 36864u + off);
                }
            }
            cp_commit();
        };

        cpW(0);
        bar_sync(1, 512);

        for (int s = 0; s < 36; ++s) {
            if (s < 35) { cpW(s + 1); cp_wait1(); }
            else        { cp_wait0(); }

            uint32_t wreg = wdst0 + (uint32_t)(s & 1) * WBUF2_B;
            uint32_t breg = smem_base + BBASE + (uint32_t)(s & 1) * BBUF_B;

#pragma unroll
            for (int ks = 0; ks < 4; ++ks) {
                // A fragments for both m-tiles, hi+lo (16 regs)
                uint32_t Ah[2][4], Al[2][4];
#pragma unroll
                for (int mt = 0; mt < 2; ++mt) {
                    uint32_t aaddr = wreg +
                        (uint32_t)((mt * 16 + a_row) * WROW + ks * 16 + a_cad) * 2;
                    ldmatrix_x4(Ah[mt][0], Ah[mt][1], Ah[mt][2], Ah[mt][3], aaddr);
                    ldmatrix_x4(Al[mt][0], Al[mt][1], Al[mt][2], Al[mt][3],
                                aaddr + BHL2_B);
                }
                // B in two pr-halves (16 frag regs live at a time)
#pragma unroll
                for (int prh = 0; prh < 2; ++prh) {
                    uint32_t Bh[8], Bl[8];
#pragma unroll
                    for (int pi = 0; pi < 2; ++pi) {
                        int pr = prh * 2 + pi;
                        uint32_t addr = breg +
                            (uint32_t)((pr * 16 + b_row) * WROW + ks * 16 + b_cad) * 2;
                        ldmatrix_x4(Bh[pi * 4 + 0], Bh[pi * 4 + 1],
                                    Bh[pi * 4 + 2], Bh[pi * 4 + 3], addr);
                        ldmatrix_x4(Bl[pi * 4 + 0], Bl[pi * 4 + 1],
                                    Bl[pi * 4 + 2], Bl[pi * 4 + 3], addr + BHL_B);
                    }
#pragma unroll
                    for (int mt = 0; mt < 2; ++mt) {
#pragma unroll
                        for (int ntl = 0; ntl < 4; ++ntl) {
                            int nt = prh * 4 + ntl;
                            uint32_t bh0 = Bh[ntl * 2], bh1 = Bh[ntl * 2 + 1];
                            uint32_t bl0 = Bl[ntl * 2], bl1 = Bl[ntl * 2 + 1];
                            float* d = acc[mt][nt];
                            mma_bf16(d[0], d[1], d[2], d[3],
                                     Ah[mt][0], Ah[mt][1], Ah[mt][2], Ah[mt][3], bh0, bh1);
                            mma_bf16(d[0], d[1], d[2], d[3],
                                     Ah[mt][0], Ah[mt][1], Ah[mt][2], Ah[mt][3], bl0, bl1);
                            mma_bf16(d[0], d[1], d[2], d[3],
                                     Al[mt][0], Al[mt][1], Al[mt][2], Al[mt][3], bh0, bh1);
                        }
                    }
                }
            }
            bar_sync(1, 512);
        }

        // ---- epilogue: BN + SiLU
#pragma unroll
        for (int mt = 0; mt < 2; ++mt) {
            int o_lo = o0 + mt * 16 + g4;
            int o_hi = o_lo + 8;
            float invl = gamma[o_lo] * rsqrtf(rvar[o_lo] + 1e-5f);
            float bbl  = beta[o_lo] - rmean[o_lo] * invl;
            float invh = gamma[o_hi] * rsqrtf(rvar[o_hi] + 1e-5f);
            float bbh  = beta[o_hi] - rmean[o_hi] * invh;
            float* opl = out + (((size_t)b * C2_ + o_lo) * H_ + h) * W_;
            float* oph = out + (((size_t)b * C2_ + o_hi) * H_ + h) * W_;
#pragma unroll
            for (int nt = 0; nt < 8; ++nt) {
                int pp = nt * 8 + t4 * 2;
                float y0v = acc[mt][nt][0] * invl + bbl;
                float y1v = acc[mt][nt][1] * invl + bbl;
                float y2v = acc[mt][nt][2] * invh + bbh;
                float y3v = acc[mt][nt][3] * invh + bbh;
                float2 vlo, vhi;
                vlo.x = y0v / (1.f + __expf(-y0v));
                vlo.y = y1v / (1.f + __expf(-y1v));
                vhi.x = y2v / (1.f + __expf(-y2v));
                vhi.y = y3v / (1.f + __expf(-y3v));
                *(float2*)(opl + pp) = vlo;
                *(float2*)(oph + pp) = vhi;
            }
        }
    }
}

// ---------------------------------------------------------------------------
extern "C" void kernel_launch(void* const* d_in, const int* in_sizes, int n_in,
                              void* d_out, int out_size) {
    const float* x      = (const float*)d_in[0];
    const float* w_off  = (const float*)d_in[1];
    const float* b_off  = (const float*)d_in[2];
    const float* w_dcn  = (const float*)d_in[3];
    const float* gamma  = (const float*)d_in[4];
    const float* beta   = (const float*)d_in[5];
    const float* rmean  = (const float*)d_in[6];
    const float* rvar   = (const float*)d_in[7];
    float* out = (float*)d_out;

    cudaFuncSetAttribute(dcn_fused, cudaFuncAttributeMaxDynamicSharedMemorySize,
                         SMEM_BYTES);

    pack_weights<<<2304, 256>>>(w_dcn, w_off);
    dcn_fused<<<B_ * H_, 512, SMEM_BYTES>>>(x, b_off, gamma, beta, rmean, rvar, out);
}

// round 8
// speedup vs baseline: 1.3417x; 1.3417x over previous
#include <cuda_runtime.h>
#include <cuda_bf16.h>
#include <cuda_fp16.h>
#include <cstdint>
#include <math.h>

// Problem constants
#define B_  2
#define C1_ 256
#define C2_ 256
#define K2_ 9
#define H_  64
#define W_  64
#define HW_ 4096

// ---------------------------------------------------------------------------
// Scratch (allocation-free: __device__ globals)
// ---------------------------------------------------------------------------
// Main weights (fp16 single): [step(36)=tap*4+chunk][o(256)][72 fp16]
__device__ __align__(128) __half g_wA[36 * 256 * 72];
// Conv weights (bf16 hi/lo): [step(36)=kk*4+chunk][hl(2)][ocpad(32)][72 bf16]
__device__ __align__(128) __nv_bfloat16 g_wC[36 * 2 * 32 * 72];

// ---------------------------------------------------------------------------
// PTX helpers (plain sm_103-legal)
// ---------------------------------------------------------------------------
__device__ __forceinline__ uint32_t smem_u32(const void* p) {
    uint32_t a;
    asm("{ .reg .u64 t; cvta.to.shared.u64 t, %1; cvt.u32.u64 %0, t; }"
        : "=r"(a) : "l"(p));
    return a;
}
__device__ __forceinline__ void cp_async16(uint32_t saddr, const void* gaddr) {
    asm volatile("cp.async.cg.shared.global [%0], [%1], 16;"
                 :: "r"(saddr), "l"(gaddr) : "memory");
}
__device__ __forceinline__ void cp_commit() {
    asm volatile("cp.async.commit_group;" ::: "memory");
}
__device__ __forceinline__ void cp_wait1() {
    asm volatile("cp.async.wait_group 1;" ::: "memory");
}
__device__ __forceinline__ void cp_wait0() {
    asm volatile("cp.async.wait_group 0;" ::: "memory");
}
__device__ __forceinline__ void bar_sync(int id, int cnt) {
    asm volatile("bar.sync %0, %1;" :: "r"(id), "r"(cnt) : "memory");
}
__device__ __forceinline__ void ldmatrix_x4(uint32_t& r0, uint32_t& r1,
                                            uint32_t& r2, uint32_t& r3,
                                            uint32_t addr) {
    asm volatile("ldmatrix.sync.aligned.m8n8.x4.shared.b16 {%0,%1,%2,%3}, [%4];"
                 : "=r"(r0), "=r"(r1), "=r"(r2), "=r"(r3) : "r"(addr));
}
__device__ __forceinline__ void mma_bf16(float& d0, float& d1, float& d2, float& d3,
                                         uint32_t a0, uint32_t a1, uint32_t a2, uint32_t a3,
                                         uint32_t b0, uint32_t b1) {
    asm volatile(
        "mma.sync.aligned.m16n8k16.row.col.f32.bf16.bf16.f32 "
        "{%0,%1,%2,%3}, {%4,%5,%6,%7}, {%8,%9}, {%0,%1,%2,%3};"
        : "+f"(d0), "+f"(d1), "+f"(d2), "+f"(d3)
        : "r"(a0), "r"(a1), "r"(a2), "r"(a3), "r"(b0), "r"(b1));
}
__device__ __forceinline__ void mma_f16(float& d0, float& d1, float& d2, float& d3,
                                        uint32_t a0, uint32_t a1, uint32_t a2, uint32_t a3,
                                        uint32_t b0, uint32_t b1) {
    asm volatile(
        "mma.sync.aligned.m16n8k16.row.col.f32.f16.f16.f32 "
        "{%0,%1,%2,%3}, {%4,%5,%6,%7}, {%8,%9}, {%0,%1,%2,%3};"
        : "+f"(d0), "+f"(d1), "+f"(d2), "+f"(d3)
        : "r"(a0), "r"(a1), "r"(a2), "r"(a3), "r"(b0), "r"(b1));
}

// ---------------------------------------------------------------------------
// Kernel 0: pack w_dcn (fp16) + w_off (bf16 hi/lo)
// ---------------------------------------------------------------------------
__global__ void pack_weights(const float* __restrict__ w_dcn,
                             const float* __restrict__ w_off) {
    int idx = blockIdx.x * 256 + threadIdx.x;
    if (idx < 9 * 256 * 256) {
        int t = idx >> 16;
        int r = idx & 65535;
        int o = r >> 8;
        int c = r & 255;
        float w = w_dcn[o * (C1_ * K2_) + c * K2_ + t];
        int chunk = c >> 6, cl = c & 63;
        g_wA[(size_t)(t * 4 + chunk) * (256 * 72) + (size_t)o * 72 + cl] =
            __float2half_rn(w);
    }
    if (idx < 27 * 2304) {
        int oc = idx / 2304;
        int r  = idx % 2304;
        int c  = r / 9;
        int kk = r % 9;
        float w = w_off[idx];
        __nv_bfloat16 hi = __float2bfloat16(w);
        __nv_bfloat16 lo = __float2bfloat16(w - __bfloat162float(hi));
        int s = kk * 4 + (c >> 6);
        int cl = c & 63;
        size_t base = (size_t)s * (2 * 32 * 72) + (size_t)oc * 72 + cl;
        g_wC[base]           = hi;
        g_wC[base + 32 * 72] = lo;
    }
}

// ---------------------------------------------------------------------------
// Fused kernel, 512 threads: warps 0-7 consumers, 8-15 producers.
// Phase 1: offset-conv GEMM (bf16 3-pass) -> om smem.
// Phase 2: DCN GEMM (fp16 1-pass) + BN + SiLU.
// ---------------------------------------------------------------------------
#define WROW     72
#define WROWB    144
// phase-1 conv weight buffers (per warp, hi+lo, double-buffered)
#define C_BHL_B   4608u
#define C_WBUF_B  9216u
#define C_WWARP_B 18432u
// phase-2 main weight buffers (per warp, fp16 single, double-buffered)
#define M_WSLICE_B 4608u
#define M_WWARP_B  9216u
// B region
#define BBASE    147456u     // 8 * C_WWARP_B
#define BBUF_B   18432u      // buffer stride (phase1 uses hi+lo; phase2 first 9216)
#define BHL_B    9216u
#define META_O   184320u
// META: swt[256]f (1024) | sidx[256]i (1024) | om[32*64]f (8192)
#define SMEM_BYTES (META_O + 2048u + 8192u)

__global__ __launch_bounds__(512, 1) void dcn_fused(const float* __restrict__ x,
                                                    const float* __restrict__ b_off,
                                                    const float* __restrict__ gamma,
                                                    const float* __restrict__ beta,
                                                    const float* __restrict__ rmean,
                                                    const float* __restrict__ rvar,
                                                    float* __restrict__ out) {
    extern __shared__ __align__(128) unsigned char smem_raw[];
    const uint32_t smem_base = smem_u32(smem_raw);

    int b = blockIdx.x >> 6;
    int h = blockIdx.x & 63;
    int tid = threadIdx.x;
    int wid = tid >> 5;
    int lane = tid & 31;

    float* swt  = (float*)(smem_raw + META_O);
    int*   sidx = (int*)(smem_raw + META_O + 1024);
    float* om   = (float*)(smem_raw + META_O + 2048);   // [oc][64]
    const float* xb = x + b * C1_ * HW_;

    if (wid >= 8) {
        // ========================= PRODUCERS (8 warps) =========================
        int ptid = tid - 256;
        int p  = ptid & 63;
        int cg = ptid >> 6;      // 0..3 -> 16 channels each

        // ---- phase 1: im2col (bf16 hi/lo)
        auto conv_chunk = [&](int s) {
            int kk = s >> 2, q = s & 3;
            int ky = kk / 3, kx = kk % 3;
            int y = h - 1 + ky;
            int col = p - 1 + kx;
            bool valid = (y >= 0) && (y < H_) && (col >= 0) && (col < W_);
            unsigned char* Bb = smem_raw + BBASE + (uint32_t)(s & 1) * BBUF_B;
            uint32_t rowoff = (uint32_t)p * WROWB;
#pragma unroll
            for (int it = 0; it < 8; ++it) {
                int cl = cg * 16 + it * 2;
                int c0 = q * 64 + cl;
                float va = 0.f, vb = 0.f;
                if (valid) {
                    const float* xa = xb + ((size_t)c0 << 12) + y * W_ + col;
                    va = xa[0];
                    vb = xa[HW_];
                }
                __nv_bfloat162 hp = __floats2bfloat162_rn(va, vb);
                float ra = va - __bfloat162float(hp.x);
                float rb = vb - __bfloat162float(hp.y);
                __nv_bfloat162 lp = __floats2bfloat162_rn(ra, rb);
                uint32_t a = rowoff + (uint32_t)cl * 2;
                *(__nv_bfloat162*)(Bb + a)         = hp;
                *(__nv_bfloat162*)(Bb + BHL_B + a) = lp;
            }
        };

        conv_chunk(0);
        bar_sync(1, 512);
        for (int s = 0; s < 36; ++s) {
            if (s < 35) conv_chunk(s + 1);
            bar_sync(1, 512);
        }
        bar_sync(1, 512);        // consumers write om

        // ---- phase 2: bilinear metadata + fp16 gather
        auto make_meta = [&](int t) {
            if (ptid < 64) {
                int w = ptid;
                float py = (float)(h - 1 + t / 3) + om[(2 * t) * 64 + w];
                float px = (float)(w - 1 + t % 3) + om[(2 * t + 1) * 64 + w];
                float m = 1.f / (1.f + __expf(-om[(18 + t) * 64 + w]));
                float y0f = floorf(py), x0f = floorf(px);
                float ly = py - y0f, lx = px - x0f;
                int y0 = (int)y0f, x0 = (int)x0f;
                int y1 = y0 + 1, x1 = x0 + 1;
                float vy0 = (y0 >= 0 && y0 < H_) ? 1.f : 0.f;
                float vy1 = (y1 >= 0 && y1 < H_) ? 1.f : 0.f;
                float vx0 = (x0 >= 0 && x0 < W_) ? 1.f : 0.f;
                float vx1 = (x1 >= 0 && x1 < W_) ? 1.f : 0.f;
                int cy0 = min(max(y0, 0), H_ - 1), cy1 = min(max(y1, 0), H_ - 1);
                int cx0 = min(max(x0, 0), W_ - 1), cx1 = min(max(x1, 0), W_ - 1);
                swt[0 * 64 + w] = (1.f - ly) * (1.f - lx) * m * vy0 * vx0;
                swt[1 * 64 + w] = (1.f - ly) * lx * m * vy0 * vx1;
                swt[2 * 64 + w] = ly * (1.f - lx) * m * vy1 * vx0;
                swt[3 * 64 + w] = ly * lx * m * vy1 * vx1;
                sidx[0 * 64 + w] = cy0 * W_ + cx0;
                sidx[1 * 64 + w] = cy0 * W_ + cx1;
                sidx[2 * 64 + w] = cy1 * W_ + cx0;
                sidx[3 * 64 + w] = cy1 * W_ + cx1;
            }
            bar_sync(2, 256);
        };

        auto make_chunk = [&](int s) {
            int q = s & 3;
            int i0 = sidx[p],       i1 = sidx[64 + p];
            int i2 = sidx[128 + p], i3 = sidx[192 + p];
            float w0 = swt[p],       w1 = swt[64 + p];
            float w2 = swt[128 + p], w3 = swt[192 + p];
            unsigned char* Bb = smem_raw + BBASE + (uint32_t)(s & 1) * BBUF_B;
            uint32_t rowoff = (uint32_t)p * WROWB;
#pragma unroll
            for (int it = 0; it < 8; ++it) {
                int cl = cg * 16 + it * 2;
                int c0 = q * 64 + cl;
                const float* xa = xb + ((size_t)c0 << 12);
                const float* xc = xa + HW_;
                float va = xa[i0] * w0 + xa[i1] * w1 + xa[i2] * w2 + xa[i3] * w3;
                float vb = xc[i0] * w0 + xc[i1] * w1 + xc[i2] * w2 + xc[i3] * w3;
                __half2 hp = __floats2half2_rn(va, vb);
                *(__half2*)(Bb + rowoff + (uint32_t)cl * 2) = hp;
            }
        };

        make_meta(0);
        make_chunk(0);
        bar_sync(1, 512);
        for (int s = 0; s < 36; ++s) {
            if (s < 35) {
                int ns = s + 1;
                if ((ns & 3) == 0) make_meta(ns >> 2);
                make_chunk(ns);
            }
            bar_sync(1, 512);
        }
    } else {
        // ========================= CONSUMERS (8 warps) =========================
        int a_row = lane & 15;
        int a_cad = (lane >= 16) ? 8 : 0;
        int b_row = (lane & 7) + ((lane >= 16) ? 8 : 0);
        int b_cad = ((lane >> 3) & 1) * 8;
        int g4 = lane >> 2;
        int t4 = lane & 3;

        // ---- phase 1: conv MMA (bf16 3-pass; m=32 oc; warp owns 8 px)
        {
            uint32_t wdst0 = smem_base + (uint32_t)wid * C_WWARP_B;
            int rgn  = wid >> 1;
            int half = wid & 1;

            float accC[2][4];
#pragma unroll
            for (int mt = 0; mt < 2; mt++)
#pragma unroll
                for (int j = 0; j < 4; j++) accC[mt][j] = 0.f;

            auto cpWC = [&](int s) {
                const unsigned char* src =
                    (const unsigned char*)g_wC + (size_t)s * 9216u;
                uint32_t dst = wdst0 + (uint32_t)(s & 1) * C_WBUF_B;
#pragma unroll
                for (int hl = 0; hl < 2; ++hl) {
#pragma unroll
                    for (int j = 0; j < 9; ++j) {       // 9*32*16B = 4608B
                        uint32_t off = (uint32_t)(lane + j * 32) * 16u;
                        cp_async16(dst + (uint32_t)hl * C_BHL_B + off,
                                   src + (size_t)hl * 4608u + off);
                    }
                }
                cp_commit();
            };

            cpWC(0);
            bar_sync(1, 512);

            for (int s = 0; s < 36; ++s) {
                if (s < 35) { cpWC(s + 1); cp_wait1(); }
                else        { cp_wait0(); }

                uint32_t wreg = wdst0 + (uint32_t)(s & 1) * C_WBUF_B;
                uint32_t breg = smem_base + BBASE + (uint32_t)(s & 1) * BBUF_B;

#pragma unroll
                for (int ks = 0; ks < 4; ++ks) {
                    uint32_t addrB = breg +
                        (uint32_t)((rgn * 16 + b_row) * WROW + ks * 16 + b_cad) * 2;
                    uint32_t Bh0, Bh1, Bh2, Bh3, Bl0, Bl1, Bl2, Bl3;
                    ldmatrix_x4(Bh0, Bh1, Bh2, Bh3, addrB);
                    ldmatrix_x4(Bl0, Bl1, Bl2, Bl3, addrB + BHL_B);
                    uint32_t bh0 = half ? Bh2 : Bh0, bh1 = half ? Bh3 : Bh1;
                    uint32_t bl0 = half ? Bl2 : Bl0, bl1 = half ? Bl3 : Bl1;
#pragma unroll
                    for (int mt = 0; mt < 2; ++mt) {
                        uint32_t aaddr = wreg +
                            (uint32_t)((mt * 16 + a_row) * WROW + ks * 16 + a_cad) * 2;
                        uint32_t Ah0, Ah1, Ah2, Ah3, Al0, Al1, Al2, Al3;
                        ldmatrix_x4(Ah0, Ah1, Ah2, Ah3, aaddr);
                        ldmatrix_x4(Al0, Al1, Al2, Al3, aaddr + C_BHL_B);
                        float* d = accC[mt];
                        mma_bf16(d[0], d[1], d[2], d[3], Ah0, Ah1, Ah2, Ah3, bh0, bh1);
                        mma_bf16(d[0], d[1], d[2], d[3], Ah0, Ah1, Ah2, Ah3, bl0, bl1);
                        mma_bf16(d[0], d[1], d[2], d[3], Al0, Al1, Al2, Al3, bh0, bh1);
                    }
                }
                bar_sync(1, 512);
            }

            // conv epilogue -> om smem (+ bias)
            int col0 = rgn * 16 + half * 8;
#pragma unroll
            for (int mt = 0; mt < 2; ++mt) {
                int oc_lo = mt * 16 + g4;
                int oc_hi = oc_lo + 8;
                int col = col0 + t4 * 2;
                if (oc_lo < 27) {
                    float bo = b_off[oc_lo];
                    om[oc_lo * 64 + col]     = accC[mt][0] + bo;
                    om[oc_lo * 64 + col + 1] = accC[mt][1] + bo;
                }
                if (oc_hi < 27) {
                    float bo = b_off[oc_hi];
                    om[oc_hi * 64 + col]     = accC[mt][2] + bo;
                    om[oc_hi * 64 + col + 1] = accC[mt][3] + bo;
                }
            }
            bar_sync(1, 512);    // om ready for producers
        }

        // ---- phase 2: main DCN MMA (fp16 1-pass; warp owns o in [32w, 32w+32))
        int o0 = wid * 32;
        float acc[2][8][4];
#pragma unroll
        for (int mt = 0; mt < 2; mt++)
#pragma unroll
            for (int nt = 0; nt < 8; nt++)
#pragma unroll
                for (int j = 0; j < 4; j++) acc[mt][nt][j] = 0.f;

        uint32_t wdst2 = smem_base + (uint32_t)wid * M_WWARP_B;
        const unsigned char* wsrc0 = (const unsigned char*)g_wA +
                                     (size_t)wid * 4608u;

        auto cpW = [&](int s) {
            const unsigned char* src = wsrc0 + (size_t)s * 36864u;
            uint32_t dst = wdst2 + (uint32_t)(s & 1) * M_WSLICE_B;
#pragma unroll
            for (int j = 0; j < 9; ++j) {               // 9*32*16B = 4608B
                uint32_t off = (uint32_t)(lane + j * 32) * 16u;
                cp_async16(dst + off, src + off);
            }
            cp_commit();
        };

        cpW(0);
        bar_sync(1, 512);

        for (int s = 0; s < 36; ++s) {
            if (s < 35) { cpW(s + 1); cp_wait1(); }
            else        { cp_wait0(); }

            uint32_t wreg = wdst2 + (uint32_t)(s & 1) * M_WSLICE_B;
            uint32_t breg = smem_base + BBASE + (uint32_t)(s & 1) * BBUF_B;

#pragma unroll
            for (int ks = 0; ks < 4; ++ks) {
                uint32_t A[2][4];
#pragma unroll
                for (int mt = 0; mt < 2; ++mt) {
                    uint32_t aaddr = wreg +
                        (uint32_t)((mt * 16 + a_row) * WROW + ks * 16 + a_cad) * 2;
                    ldmatrix_x4(A[mt][0], A[mt][1], A[mt][2], A[mt][3], aaddr);
                }
                uint32_t Bf[16];
#pragma unroll
                for (int pr = 0; pr < 4; ++pr) {
                    uint32_t addr = breg +
                        (uint32_t)((pr * 16 + b_row) * WROW + ks * 16 + b_cad) * 2;
                    ldmatrix_x4(Bf[pr * 4 + 0], Bf[pr * 4 + 1],
                                Bf[pr * 4 + 2], Bf[pr * 4 + 3], addr);
                }
#pragma unroll
                for (int mt = 0; mt < 2; ++mt) {
#pragma unroll
                    for (int nt = 0; nt < 8; ++nt) {
                        float* d = acc[mt][nt];
                        mma_f16(d[0], d[1], d[2], d[3],
                                A[mt][0], A[mt][1], A[mt][2], A[mt][3],
                                Bf[nt * 2], Bf[nt * 2 + 1]);
                    }
                }
            }
            bar_sync(1, 512);
        }

        // ---- epilogue: BN + SiLU
#pragma unroll
        for (int mt = 0; mt < 2; ++mt) {
            int o_lo = o0 + mt * 16 + g4;
            int o_hi = o_lo + 8;
            float invl = gamma[o_lo] * rsqrtf(rvar[o_lo] + 1e-5f);
            float bbl  = beta[o_lo] - rmean[o_lo] * invl;
            float invh = gamma[o_hi] * rsqrtf(rvar[o_hi] + 1e-5f);
            float bbh  = beta[o_hi] - rmean[o_hi] * invh;
            float* opl = out + (((size_t)b * C2_ + o_lo) * H_ + h) * W_;
            float* oph = out + (((size_t)b * C2_ + o_hi) * H_ + h) * W_;
#pragma unroll
            for (int nt = 0; nt < 8; ++nt) {
                int pp = nt * 8 + t4 * 2;
                float y0v = acc[mt][nt][0] * invl + bbl;
                float y1v = acc[mt][nt][1] * invl + bbl;
                float y2v = acc[mt][nt][2] * invh + bbh;
                float y3v = acc[mt][nt][3] * invh + bbh;
                float2 vlo, vhi;
                vlo.x = y0v / (1.f + __expf(-y0v));
                vlo.y = y1v / (1.f + __expf(-y1v));
                vhi.x = y2v / (1.f + __expf(-y2v));
                vhi.y = y3v / (1.f + __expf(-y3v));
                *(float2*)(opl + pp) = vlo;
                *(float2*)(oph + pp) = vhi;
            }
        }
    }
}

// ---------------------------------------------------------------------------
extern "C" void kernel_launch(void* const* d_in, const int* in_sizes, int n_in,
                              void* d_out, int out_size) {
    const float* x      = (const float*)d_in[0];
    const float* w_off  = (const float*)d_in[1];
    const float* b_off  = (const float*)d_in[2];
    const float* w_dcn  = (const float*)d_in[3];
    const float* gamma  = (const float*)d_in[4];
    const float* beta   = (const float*)d_in[5];
    const float* rmean  = (const float*)d_in[6];
    const float* rvar   = (const float*)d_in[7];
    float* out = (float*)d_out;

    cudaFuncSetAttribute(dcn_fused, cudaFuncAttributeMaxDynamicSharedMemorySize,
                         SMEM_BYTES);

    pack_weights<<<2304, 256>>>(w_dcn, w_off);
    dcn_fused<<<B_ * H_, 512, SMEM_BYTES>>>(x, b_off, gamma, beta, rmean, rvar, out);
}

// round 9
// speedup vs baseline: 1.6819x; 1.2536x over previous
#include <cuda_runtime.h>
#include <cuda_bf16.h>
#include <cuda_fp16.h>
#include <cstdint>
#include <math.h>

// Problem constants
#define B_  2
#define C1_ 256
#define C2_ 256
#define K2_ 9
#define H_  64
#define W_  64
#define HW_ 4096

// ---------------------------------------------------------------------------
// Scratch (allocation-free: __device__ globals; zero-init covers pad cols)
// ---------------------------------------------------------------------------
// Main weights fp16: [step(18)=tap*2+half][o(256)][136] (128 c + 8 pad)
__device__ __align__(128) __half g_wA[18 * 256 * 136];
// Conv weights fp16: [step(18)=kk*2+half][ocpad(32)][136]
__device__ __align__(128) __half g_wC[18 * 32 * 136];

// ---------------------------------------------------------------------------
// PTX helpers (plain sm_103-legal)
// ---------------------------------------------------------------------------
__device__ __forceinline__ uint32_t smem_u32(const void* p) {
    uint32_t a;
    asm("{ .reg .u64 t; cvta.to.shared.u64 t, %1; cvt.u32.u64 %0, t; }"
        : "=r"(a) : "l"(p));
    return a;
}
__device__ __forceinline__ void cp_async16(uint32_t saddr, const void* gaddr) {
    asm volatile("cp.async.cg.shared.global [%0], [%1], 16;"
                 :: "r"(saddr), "l"(gaddr) : "memory");
}
__device__ __forceinline__ void cp_commit() {
    asm volatile("cp.async.commit_group;" ::: "memory");
}
__device__ __forceinline__ void cp_wait1() {
    asm volatile("cp.async.wait_group 1;" ::: "memory");
}
__device__ __forceinline__ void cp_wait0() {
    asm volatile("cp.async.wait_group 0;" ::: "memory");
}
__device__ __forceinline__ void bar_sync(int id, int cnt) {
    asm volatile("bar.sync %0, %1;" :: "r"(id), "r"(cnt) : "memory");
}
__device__ __forceinline__ void ldmatrix_x4(uint32_t& r0, uint32_t& r1,
                                            uint32_t& r2, uint32_t& r3,
                                            uint32_t addr) {
    asm volatile("ldmatrix.sync.aligned.m8n8.x4.shared.b16 {%0,%1,%2,%3}, [%4];"
                 : "=r"(r0), "=r"(r1), "=r"(r2), "=r"(r3) : "r"(addr));
}
__device__ __forceinline__ void mma_f16(float& d0, float& d1, float& d2, float& d3,
                                        uint32_t a0, uint32_t a1, uint32_t a2, uint32_t a3,
                                        uint32_t b0, uint32_t b1) {
    asm volatile(
        "mma.sync.aligned.m16n8k16.row.col.f32.f16.f16.f32 "
        "{%0,%1,%2,%3}, {%4,%5,%6,%7}, {%8,%9}, {%0,%1,%2,%3};"
        : "+f"(d0), "+f"(d1), "+f"(d2), "+f"(d3)
        : "r"(a0), "r"(a1), "r"(a2), "r"(a3), "r"(b0), "r"(b1));
}

// ---------------------------------------------------------------------------
// Kernel 0: pack w_dcn + w_off into fp16 blobs (K-chunk = 128)
// ---------------------------------------------------------------------------
__global__ void pack_weights(const float* __restrict__ w_dcn,
                             const float* __restrict__ w_off) {
    int idx = blockIdx.x * 256 + threadIdx.x;
    if (idx < 9 * 256 * 256) {
        int t = idx >> 16;
        int r = idx & 65535;
        int o = r >> 8;
        int c = r & 255;
        float w = w_dcn[o * (C1_ * K2_) + c * K2_ + t];
        int s = t * 2 + (c >> 7);
        int cl = c & 127;
        g_wA[(size_t)s * (256 * 136) + (size_t)o * 136 + cl] = __float2half_rn(w);
    }
    if (idx < 27 * 2304) {
        int oc = idx / 2304;
        int r  = idx % 2304;
        int c  = r / 9;
        int kk = r % 9;
        int s = kk * 2 + (c >> 7);
        int cl = c & 127;
        g_wC[(size_t)s * (32 * 136) + (size_t)oc * 136 + cl] =
            __float2half_rn(w_off[idx]);
    }
}

// ---------------------------------------------------------------------------
// Fused kernel, 512 threads: warps 0-7 consumers, 8-15 producers.
// Phase 1: offset-conv GEMM (fp16, 18 steps) -> om smem.
// Phase 2: DCN GEMM (fp16, 18 steps) + BN + SiLU.
// K-chunk = 128 channels per step.
// ---------------------------------------------------------------------------
#define WROW      136          // fp16 elems per row (128 + 8 pad)
#define WROWB     272          // bytes per row
#define WSLICE_B  8704u        // 32 rows x 272B (one weight buffer per warp)
#define WWARP_B   17408u       // double-buffered
#define BBASE     139264u      // 8 * WWARP_B
#define BBUF_B    17408u       // 64 rows x 272B
#define META_O    174080u      // BBASE + 2*BBUF_B
// META: swt[256]f (1024) | sidx[256]i (1024) | om[32*64]f (8192)
#define SMEM_BYTES (META_O + 2048u + 8192u)

__global__ __launch_bounds__(512, 1) void dcn_fused(const float* __restrict__ x,
                                                    const float* __restrict__ b_off,
                                                    const float* __restrict__ gamma,
                                                    const float* __restrict__ beta,
                                                    const float* __restrict__ rmean,
                                                    const float* __restrict__ rvar,
                                                    float* __restrict__ out) {
    extern __shared__ __align__(128) unsigned char smem_raw[];
    const uint32_t smem_base = smem_u32(smem_raw);

    int b = blockIdx.x >> 6;
    int h = blockIdx.x & 63;
    int tid = threadIdx.x;
    int wid = tid >> 5;
    int lane = tid & 31;

    float* swt  = (float*)(smem_raw + META_O);
    int*   sidx = (int*)(smem_raw + META_O + 1024);
    float* om   = (float*)(smem_raw + META_O + 2048);   // [oc][64]
    const float* xb = x + b * C1_ * HW_;

    if (wid >= 8) {
        // ========================= PRODUCERS (8 warps) =========================
        int ptid = tid - 256;
        int p  = ptid & 63;
        int cg = ptid >> 6;      // 0..3 -> 32 channels each (of 128-chunk)

        // ---- phase 1: im2col fp16, chunk = 128 c (step s: kk=s>>1, q=s&1)
        auto conv_chunk = [&](int s) {
            int kk = s >> 1, q = s & 1;
            int ky = kk / 3, kx = kk % 3;
            int y = h - 1 + ky;
            int col = p - 1 + kx;
            bool valid = (y >= 0) && (y < H_) && (col >= 0) && (col < W_);
            unsigned char* Bb = smem_raw + BBASE + (uint32_t)(s & 1) * BBUF_B;
            uint32_t rowoff = (uint32_t)p * WROWB;
#pragma unroll
            for (int it = 0; it < 16; ++it) {
                int cl = cg * 32 + it * 2;
                int c0 = q * 128 + cl;
                float va = 0.f, vb = 0.f;
                if (valid) {
                    const float* xa = xb + ((size_t)c0 << 12) + y * W_ + col;
                    va = xa[0];
                    vb = xa[HW_];
                }
                *(__half2*)(Bb + rowoff + (uint32_t)cl * 2) = __floats2half2_rn(va, vb);
            }
        };

        conv_chunk(0);
        bar_sync(1, 512);
        for (int s = 0; s < 18; ++s) {
            if (s < 17) conv_chunk(s + 1);
            bar_sync(1, 512);
        }
        bar_sync(1, 512);        // consumers write om

        // ---- phase 2: bilinear metadata + fp16 gather
        auto make_meta = [&](int t) {
            if (ptid < 64) {
                int w = ptid;
                float py = (float)(h - 1 + t / 3) + om[(2 * t) * 64 + w];
                float px = (float)(w - 1 + t % 3) + om[(2 * t + 1) * 64 + w];
                float m = 1.f / (1.f + __expf(-om[(18 + t) * 64 + w]));
                float y0f = floorf(py), x0f = floorf(px);
                float ly = py - y0f, lx = px - x0f;
                int y0 = (int)y0f, x0 = (int)x0f;
                int y1 = y0 + 1, x1 = x0 + 1;
                float vy0 = (y0 >= 0 && y0 < H_) ? 1.f : 0.f;
                float vy1 = (y1 >= 0 && y1 < H_) ? 1.f : 0.f;
                float vx0 = (x0 >= 0 && x0 < W_) ? 1.f : 0.f;
                float vx1 = (x1 >= 0 && x1 < W_) ? 1.f : 0.f;
                int cy0 = min(max(y0, 0), H_ - 1), cy1 = min(max(y1, 0), H_ - 1);
                int cx0 = min(max(x0, 0), W_ - 1), cx1 = min(max(x1, 0), W_ - 1);
                swt[0 * 64 + w] = (1.f - ly) * (1.f - lx) * m * vy0 * vx0;
                swt[1 * 64 + w] = (1.f - ly) * lx * m * vy0 * vx1;
                swt[2 * 64 + w] = ly * (1.f - lx) * m * vy1 * vx0;
                swt[3 * 64 + w] = ly * lx * m * vy1 * vx1;
                sidx[0 * 64 + w] = cy0 * W_ + cx0;
                sidx[1 * 64 + w] = cy0 * W_ + cx1;
                sidx[2 * 64 + w] = cy1 * W_ + cx0;
                sidx[3 * 64 + w] = cy1 * W_ + cx1;
            }
            bar_sync(2, 256);
        };

        auto make_chunk = [&](int s) {
            int q = s & 1;
            int i0 = sidx[p],       i1 = sidx[64 + p];
            int i2 = sidx[128 + p], i3 = sidx[192 + p];
            float w0 = swt[p],       w1 = swt[64 + p];
            float w2 = swt[128 + p], w3 = swt[192 + p];
            unsigned char* Bb = smem_raw + BBASE + (uint32_t)(s & 1) * BBUF_B;
            uint32_t rowoff = (uint32_t)p * WROWB;
#pragma unroll
            for (int it = 0; it < 16; ++it) {
                int cl = cg * 32 + it * 2;
                int c0 = q * 128 + cl;
                const float* xa = xb + ((size_t)c0 << 12);
                const float* xc = xa + HW_;
                float va = xa[i0] * w0 + xa[i1] * w1 + xa[i2] * w2 + xa[i3] * w3;
                float vb = xc[i0] * w0 + xc[i1] * w1 + xc[i2] * w2 + xc[i3] * w3;
                *(__half2*)(Bb + rowoff + (uint32_t)cl * 2) = __floats2half2_rn(va, vb);
            }
        };

        make_meta(0);
        make_chunk(0);
        bar_sync(1, 512);
        for (int s = 0; s < 18; ++s) {
            if (s < 17) {
                int ns = s + 1;
                if ((ns & 1) == 0) make_meta(ns >> 1);
                make_chunk(ns);
            }
            bar_sync(1, 512);
        }
    } else {
        // ========================= CONSUMERS (8 warps) =========================
        int a_row = lane & 15;
        int a_cad = (lane >= 16) ? 8 : 0;
        int b_row = (lane & 7) + ((lane >= 16) ? 8 : 0);
        int b_cad = ((lane >> 3) & 1) * 8;
        int g4 = lane >> 2;
        int t4 = lane & 3;

        uint32_t wdst0 = smem_base + (uint32_t)wid * WWARP_B;

        // ---- phase 1: conv MMA (fp16; m=32 oc; warp owns 8 px)
        {
            int rgn  = wid >> 1;        // 16-px region
            int half = wid & 1;         // 8-px n-tile within region

            float accC[2][4];
#pragma unroll
            for (int mt = 0; mt < 2; mt++)
#pragma unroll
                for (int j = 0; j < 4; j++) accC[mt][j] = 0.f;

            auto cpWC = [&](int s) {
                const unsigned char* src =
                    (const unsigned char*)g_wC + (size_t)s * 8704u;
                uint32_t dst = wdst0 + (uint32_t)(s & 1) * WSLICE_B;
#pragma unroll
                for (int j = 0; j < 17; ++j) {          // 17*32*16B = 8704B
                    uint32_t off = (uint32_t)(lane + j * 32) * 16u;
                    cp_async16(dst + off, src + off);
                }
                cp_commit();
            };

            cpWC(0);
            bar_sync(1, 512);

            for (int s = 0; s < 18; ++s) {
                if (s < 17) { cpWC(s + 1); cp_wait1(); }
                else        { cp_wait0(); }

                uint32_t wreg = wdst0 + (uint32_t)(s & 1) * WSLICE_B;
                uint32_t breg = smem_base + BBASE + (uint32_t)(s & 1) * BBUF_B;

#pragma unroll
                for (int ks = 0; ks < 8; ++ks) {
                    uint32_t addrB = breg +
                        (uint32_t)((rgn * 16 + b_row) * WROW + ks * 16 + b_cad) * 2;
                    uint32_t B0, B1, B2, B3;
                    ldmatrix_x4(B0, B1, B2, B3, addrB);
                    uint32_t b0 = half ? B2 : B0, b1 = half ? B3 : B1;
#pragma unroll
                    for (int mt = 0; mt < 2; ++mt) {
                        uint32_t aaddr = wreg +
                            (uint32_t)((mt * 16 + a_row) * WROW + ks * 16 + a_cad) * 2;
                        uint32_t A0, A1, A2, A3;
                        ldmatrix_x4(A0, A1, A2, A3, aaddr);
                        float* d = accC[mt];
                        mma_f16(d[0], d[1], d[2], d[3], A0, A1, A2, A3, b0, b1);
                    }
                }
                bar_sync(1, 512);
            }

            // conv epilogue -> om smem (+ bias)
            int col0 = rgn * 16 + half * 8;
#pragma unroll
            for (int mt = 0; mt < 2; ++mt) {
                int oc_lo = mt * 16 + g4;
                int oc_hi = oc_lo + 8;
                int col = col0 + t4 * 2;
                if (oc_lo < 27) {
                    float bo = b_off[oc_lo];
                    om[oc_lo * 64 + col]     = accC[mt][0] + bo;
                    om[oc_lo * 64 + col + 1] = accC[mt][1] + bo;
                }
                if (oc_hi < 27) {
                    float bo = b_off[oc_hi];
                    om[oc_hi * 64 + col]     = accC[mt][2] + bo;
                    om[oc_hi * 64 + col + 1] = accC[mt][3] + bo;
                }
            }
            bar_sync(1, 512);    // om ready for producers
        }

        // ---- phase 2: main DCN MMA (fp16; warp owns o in [32w, 32w+32))
        int o0 = wid * 32;
        float acc[2][8][4];
#pragma unroll
        for (int mt = 0; mt < 2; mt++)
#pragma unroll
            for (int nt = 0; nt < 8; nt++)
#pragma unroll
                for (int j = 0; j < 4; j++) acc[mt][nt][j] = 0.f;

        const unsigned char* wsrc0 = (const unsigned char*)g_wA +
                                     (size_t)wid * 8704u;

        auto cpW = [&](int s) {
            const unsigned char* src = wsrc0 + (size_t)s * 69632u;
            uint32_t dst = wdst0 + (uint32_t)(s & 1) * WSLICE_B;
#pragma unroll
            for (int j = 0; j < 17; ++j) {              // 17*32*16B = 8704B
                uint32_t off = (uint32_t)(lane + j * 32) * 16u;
                cp_async16(dst + off, src + off);
            }
            cp_commit();
        };

        cpW(0);
        bar_sync(1, 512);

        for (int s = 0; s < 18; ++s) {
            if (s < 17) { cpW(s + 1); cp_wait1(); }
            else        { cp_wait0(); }

            uint32_t wreg = wdst0 + (uint32_t)(s & 1) * WSLICE_B;
            uint32_t breg = smem_base + BBASE + (uint32_t)(s & 1) * BBUF_B;

#pragma unroll
            for (int ks = 0; ks < 8; ++ks) {
                uint32_t A[2][4];
#pragma unroll
                for (int mt = 0; mt < 2; ++mt) {
                    uint32_t aaddr = wreg +
                        (uint32_t)((mt * 16 + a_row) * WROW + ks * 16 + a_cad) * 2;
                    ldmatrix_x4(A[mt][0], A[mt][1], A[mt][2], A[mt][3], aaddr);
                }
                uint32_t Bf[16];
#pragma unroll
                for (int pr = 0; pr < 4; ++pr) {
                    uint32_t addr = breg +
                        (uint32_t)((pr * 16 + b_row) * WROW + ks * 16 + b_cad) * 2;
                    ldmatrix_x4(Bf[pr * 4 + 0], Bf[pr * 4 + 1],
                                Bf[pr * 4 + 2], Bf[pr * 4 + 3], addr);
                }
#pragma unroll
                for (int mt = 0; mt < 2; ++mt) {
#pragma unroll
                    for (int nt = 0; nt < 8; ++nt) {
                        float* d = acc[mt][nt];
                        mma_f16(d[0], d[1], d[2], d[3],
                                A[mt][0], A[mt][1], A[mt][2], A[mt][3],
                                Bf[nt * 2], Bf[nt * 2 + 1]);
                    }
                }
            }
            bar_sync(1, 512);
        }

        // ---- epilogue: BN + SiLU
#pragma unroll
        for (int mt = 0; mt < 2; ++mt) {
            int o_lo = o0 + mt * 16 + g4;
            int o_hi = o_lo + 8;
            float invl = gamma[o_lo] * rsqrtf(rvar[o_lo] + 1e-5f);
            float bbl  = beta[o_lo] - rmean[o_lo] * invl;
            float invh = gamma[o_hi] * rsqrtf(rvar[o_hi] + 1e-5f);
            float bbh  = beta[o_hi] - rmean[o_hi] * invh;
            float* opl = out + (((size_t)b * C2_ + o_lo) * H_ + h) * W_;
            float* oph = out + (((size_t)b * C2_ + o_hi) * H_ + h) * W_;
#pragma unroll
            for (int nt = 0; nt < 8; ++nt) {
                int pp = nt * 8 + t4 * 2;
                float y0v = acc[mt][nt][0] * invl + bbl;
                float y1v = acc[mt][nt][1] * invl + bbl;
                float y2v = acc[mt][nt][2] * invh + bbh;
                float y3v = acc[mt][nt][3] * invh + bbh;
                float2 vlo, vhi;
                vlo.x = y0v / (1.f + __expf(-y0v));
                vlo.y = y1v / (1.f + __expf(-y1v));
                vhi.x = y2v / (1.f + __expf(-y2v));
                vhi.y = y3v / (1.f + __expf(-y3v));
                *(float2*)(opl + pp) = vlo;
                *(float2*)(oph + pp) = vhi;
            }
        }
    }
}

// ---------------------------------------------------------------------------
extern "C" void kernel_launch(void* const* d_in, const int* in_sizes, int n_in,
                              void* d_out, int out_size) {
    const float* x      = (const float*)d_in[0];
    const float* w_off  = (const float*)d_in[1];
    const float* b_off  = (const float*)d_in[2];
    const float* w_dcn  = (const float*)d_in[3];
    const float* gamma  = (const float*)d_in[4];
    const float* beta   = (const float*)d_in[5];
    const float* rmean  = (const float*)d_in[6];
    const float* rvar   = (const float*)d_in[7];
    float* out = (float*)d_out;

    cudaFuncSetAttribute(dcn_fused, cudaFuncAttributeMaxDynamicSharedMemorySize,
                         SMEM_BYTES);

    pack_weights<<<2304, 256>>>(w_dcn, w_off);
    dcn_fused<<<B_ * H_, 512, SMEM_BYTES>>>(x, b_off, gamma, beta, rmean, rvar, out);
}